// round 6
// baseline (speedup 1.0000x reference)
#include <cuda_runtime.h>
#include <cuda_bf16.h>
#include <stdint.h>

// Problem constants (fixed by the dataset)
#define N_NODES_MAX 50000
#define N_EDGES_MAX 800000
#define IN_F   128
#define HID    256
#define HID2   128
#define N_CLS  2

// ---------------- scratch (static device globals; no allocation) -------------
__device__ int   g_i64;                              // 1 if edge_index is int64
__device__ int   g_deg[N_NODES_MAX];
__device__ int   g_off[N_NODES_MAX + 1];
__device__ int   g_cursor[N_NODES_MAX];
__device__ __align__(16) float g_deginv[N_NODES_MAX];
__device__ __align__(16) int   g_src[N_EDGES_MAX];   // CSR: src node per in-edge (grouped by dst)
__device__ __align__(16) float g_agg[(size_t)N_NODES_MAX * HID];   // agg buffer (max width 256)
__device__ __align__(16) float g_h1 [(size_t)N_NODES_MAX * HID];   // layer-1 activations [N,256]
__device__ __align__(16) float g_h2 [(size_t)N_NODES_MAX * HID2];  // layer-2 activations [N,128]

__device__ __forceinline__ void f4_acc(float4& a, const float4& v) {
    a.x += v.x; a.y += v.y; a.z += v.z; a.w += v.w;
}

// Read edge value e from the row (idx=0) or col (idx=1) stream, honoring dtype.
__device__ __forceinline__ int edge_at(const void* edges, int E, int which, int e) {
    if (g_i64) {
        const long long* p = (const long long*)edges;
        return (int)p[(size_t)which * E + e];
    } else {
        const int* p = (const int*)edges;
        return p[(size_t)which * E + e];
    }
}

// ---------------- dtype detect -----------------------------------------------
// If the buffer holds int64 values < 2^31, every odd 32-bit word is 0.
// With int32 node ids (uniform in [0,50000)), a long run of odd words all being
// zero has probability ~0. Single block, deterministic.
__global__ void detect_dtype_kernel(const int* __restrict__ raw, int E) {
    __shared__ int nz;
    if (threadIdx.x == 0) nz = 0;
    __syncthreads();
    int samples = min(1024, E);   // stay well inside the buffer for any dtype
    for (int i = threadIdx.x; i < samples; i += blockDim.x) {
        if (raw[2 * i + 1] != 0) atomicOr(&nz, 1);
    }
    __syncthreads();
    if (threadIdx.x == 0) g_i64 = (nz == 0) ? 1 : 0;
}

// ---------------- CSR build --------------------------------------------------
__global__ void zero_deg_kernel(int n) {
    int i = blockIdx.x * blockDim.x + threadIdx.x;
    if (i < n) g_deg[i] = 0;
}

__global__ void hist_kernel(const void* __restrict__ edges, int E, int n) {
    int e = blockIdx.x * blockDim.x + threadIdx.x;
    if (e < E) {
        int d = edge_at(edges, E, 1, e);     // col
        d = max(0, min(d, n - 1));           // defensive clamp
        atomicAdd(&g_deg[d], 1);
    }
}

// Single-block exclusive scan over g_deg -> g_off / g_cursor, plus deg_inv.
__global__ void scan_kernel(int n) {
    __shared__ int sums[1024];
    int t = threadIdx.x;
    int chunk = (n + 1023) >> 10;
    int start = min(t * chunk, n);
    int end   = min(start + chunk, n);
    int s = 0;
    for (int i = start; i < end; ++i) s += g_deg[i];
    sums[t] = s;
    __syncthreads();
    for (int d = 1; d < 1024; d <<= 1) {      // Hillis-Steele inclusive scan
        int v = (t >= d) ? sums[t - d] : 0;
        __syncthreads();
        sums[t] += v;
        __syncthreads();
    }
    int run = (t == 0) ? 0 : sums[t - 1];
    for (int i = start; i < end; ++i) {
        int d = g_deg[i];
        g_off[i]    = run;
        g_cursor[i] = run;
        g_deginv[i] = 1.0f / fmaxf((float)d, 1.0f);
        run += d;
    }
    if (t == 1023) g_off[n] = sums[1023];
}

__global__ void scatter_kernel(const void* __restrict__ edges, int E, int n) {
    int e = blockIdx.x * blockDim.x + threadIdx.x;
    if (e < E) {
        int d = edge_at(edges, E, 1, e);     // col (dst)
        d = max(0, min(d, n - 1));
        int s = edge_at(edges, E, 0, e);     // row (src)
        s = max(0, min(s, n - 1));
        int p = atomicAdd(&g_cursor[d], 1);
        if (p >= 0 && p < N_EDGES_MAX) g_src[p] = s;
    }
}

// ---------------- aggregation: warp per node, float4 gathers ------------------
// g_agg[node][:] = deg_inv[node] * sum_{s in in(node)} feat[s][:]
// FROM_X=true : feat = x parameter (width IN_F=128)
// FROM_X=false: feat = g_h1        (width HID=256)
template <int F, bool FROM_X>
__global__ void agg_kernel(const float* __restrict__ xin, int M) {
    const float* __restrict__ feat = FROM_X ? xin : (const float*)g_h1;
    int gw   = (blockIdx.x * blockDim.x + threadIdx.x) >> 5;
    int lane = threadIdx.x & 31;
    if (gw >= M) return;
    int beg = g_off[gw];
    int end = g_off[gw + 1];

    float4 acc0 = make_float4(0.f, 0.f, 0.f, 0.f);
    float4 acc1 = make_float4(0.f, 0.f, 0.f, 0.f);

    int i = beg;
    for (; i + 1 < end; i += 2) {
        int s0 = g_src[i];
        int s1 = g_src[i + 1];
        const float4* r0 = (const float4*)(feat + (size_t)s0 * F);
        const float4* r1 = (const float4*)(feat + (size_t)s1 * F);
        float4 v0 = r0[lane];
        float4 v1 = r1[lane];
        f4_acc(acc0, v0);
        f4_acc(acc0, v1);
        if (F == 256) {
            float4 w0 = r0[lane + 32];
            float4 w1 = r1[lane + 32];
            f4_acc(acc1, w0);
            f4_acc(acc1, w1);
        }
    }
    if (i < end) {
        int s0 = g_src[i];
        const float4* r0 = (const float4*)(feat + (size_t)s0 * F);
        f4_acc(acc0, r0[lane]);
        if (F == 256) f4_acc(acc1, r0[lane + 32]);
    }

    float dinv = g_deginv[gw];
    float4* o = (float4*)((float*)g_agg + (size_t)gw * F);
    acc0.x *= dinv; acc0.y *= dinv; acc0.z *= dinv; acc0.w *= dinv;
    o[lane] = acc0;
    if (F == 256) {
        acc1.x *= dinv; acc1.y *= dinv; acc1.z *= dinv; acc1.w *= dinv;
        o[lane + 32] = acc1;
    }
}

// ---------------- tiled SGEMM: C[M,N] = g_agg[M,K] @ W[N,K]^T + bias, ReLU ----
// Tile 64x64, BK=16, 256 threads, 4x4 per-thread micro-tile.
// OUT=1 -> writes g_h1 ; OUT=2 -> writes g_h2.
template <int K, int OUT>
__global__ void gemm_bias_kernel(const float* __restrict__ W,
                                 const float* __restrict__ bias,
                                 int M, int N) {
    const float* __restrict__ A = (const float*)g_agg;
    float* __restrict__ C = (OUT == 1) ? (float*)g_h1 : (float*)g_h2;

    __shared__ float As[16][64];
    __shared__ float Bs[16][64];

    int tid = threadIdx.x;           // 0..255
    int tx  = tid & 15;              // N micro
    int ty  = tid >> 4;              // M micro
    int m0  = blockIdx.y * 64;
    int n0  = blockIdx.x * 64;

    float acc[4][4];
    #pragma unroll
    for (int i = 0; i < 4; ++i)
        #pragma unroll
        for (int j = 0; j < 4; ++j) acc[i][j] = 0.f;

    int lr = tid >> 4;   // row within 64-tile (+16*i)
    int lc = tid & 15;   // k within 16

    for (int k0 = 0; k0 < K; k0 += 16) {
        #pragma unroll
        for (int i = 0; i < 4; ++i) {
            int m = m0 + lr + i * 16;
            float a = (m < M) ? A[(size_t)m * K + k0 + lc] : 0.f;
            As[lc][lr + i * 16] = a;
            int n = n0 + lr + i * 16;           // N is a multiple of 64 here
            Bs[lc][lr + i * 16] = W[(size_t)n * K + k0 + lc];
        }
        __syncthreads();

        #pragma unroll
        for (int kk = 0; kk < 16; ++kk) {
            float4 a = *(const float4*)&As[kk][ty * 4];
            float4 b = *(const float4*)&Bs[kk][tx * 4];
            acc[0][0] += a.x * b.x; acc[0][1] += a.x * b.y; acc[0][2] += a.x * b.z; acc[0][3] += a.x * b.w;
            acc[1][0] += a.y * b.x; acc[1][1] += a.y * b.y; acc[1][2] += a.y * b.z; acc[1][3] += a.y * b.w;
            acc[2][0] += a.z * b.x; acc[2][1] += a.z * b.y; acc[2][2] += a.z * b.z; acc[2][3] += a.z * b.w;
            acc[3][0] += a.w * b.x; acc[3][1] += a.w * b.y; acc[3][2] += a.w * b.z; acc[3][3] += a.w * b.w;
        }
        __syncthreads();
    }

    #pragma unroll
    for (int i = 0; i < 4; ++i) {
        int m = m0 + ty * 4 + i;
        if (m >= M) continue;
        #pragma unroll
        for (int j = 0; j < 4; ++j) {
            int n = n0 + tx * 4 + j;
            float v = acc[i][j] + bias[n];
            v = fmaxf(v, 0.f);                 // both layers ReLU
            C[(size_t)m * N + n] = v;
        }
    }
}

// ---------------- final head: out[N,2] = g_h2 @ W3^T + b3 ---------------------
__global__ void head_kernel(const float* __restrict__ W3,
                            const float* __restrict__ b3,
                            float* __restrict__ out, int M) {
    __shared__ float w[2][HID2];
    __shared__ float b[2];
    for (int i = threadIdx.x; i < 2 * HID2; i += blockDim.x)
        w[i / HID2][i % HID2] = W3[i];
    if (threadIdx.x < 2) b[threadIdx.x] = b3[threadIdx.x];
    __syncthreads();

    int n = blockIdx.x * blockDim.x + threadIdx.x;
    if (n >= M) return;
    const float4* r = (const float4*)((const float*)g_h2 + (size_t)n * HID2);
    float s0 = b[0], s1 = b[1];
    #pragma unroll
    for (int i = 0; i < HID2 / 4; ++i) {
        float4 v = r[i];
        s0 += v.x * w[0][4 * i] + v.y * w[0][4 * i + 1] + v.z * w[0][4 * i + 2] + v.w * w[0][4 * i + 3];
        s1 += v.x * w[1][4 * i] + v.y * w[1][4 * i + 1] + v.z * w[1][4 * i + 2] + v.w * w[1][4 * i + 3];
    }
    out[(size_t)n * 2 + 0] = s0;
    out[(size_t)n * 2 + 1] = s1;
}

// ---------------- launch -----------------------------------------------------
extern "C" void kernel_launch(void* const* d_in, const int* in_sizes, int n_in,
                              void* d_out, int out_size) {
    const float* x     = (const float*)d_in[0];
    const void*  edges = d_in[1];            // [2, E], int32 OR int64 (detected on device)

    // Robust input layout: the n_nodes scalar may or may not be shipped as an
    // input buffer. Detect it by element count (scalar => size <= 1).
    int wbase = 2;
    if (n_in >= 9 && in_sizes[2] <= 1) wbase = 3;
    const float* W1 = (const float*)d_in[wbase + 0];
    const float* b1 = (const float*)d_in[wbase + 1];
    const float* W2 = (const float*)d_in[wbase + 2];
    const float* b2 = (const float*)d_in[wbase + 3];
    const float* W3 = (const float*)d_in[wbase + 4];
    const float* b3 = (const float*)d_in[wbase + 5];
    float* out = (float*)d_out;

    int N = in_sizes[0] / IN_F;          // 50000
    int E = in_sizes[1] / 2;             // 800000
    if (N > N_NODES_MAX) N = N_NODES_MAX;
    if (E > N_EDGES_MAX) E = N_EDGES_MAX;

    // dtype detect + CSR build
    detect_dtype_kernel<<<1, 256>>>((const int*)edges, E);
    zero_deg_kernel<<<(N + 255) / 256, 256>>>(N);
    hist_kernel<<<(E + 255) / 256, 256>>>(edges, E, N);
    scan_kernel<<<1, 1024>>>(N);
    scatter_kernel<<<(E + 255) / 256, 256>>>(edges, E, N);

    const int warpsPerBlock = 8;
    int aggBlocks = (N + warpsPerBlock - 1) / warpsPerBlock;

    // layer 1: agg(x) -> g_agg ; gemm(g_agg, W1) -> g_h1 (ReLU)
    agg_kernel<IN_F, true><<<aggBlocks, warpsPerBlock * 32>>>(x, N);
    {
        dim3 grid(HID / 64, (N + 63) / 64);
        gemm_bias_kernel<IN_F, 1><<<grid, 256>>>(W1, b1, N, HID);
    }
    // layer 2: agg(g_h1) -> g_agg ; gemm(g_agg, W2) -> g_h2 (ReLU)
    agg_kernel<HID, false><<<aggBlocks, warpsPerBlock * 32>>>(x, N);
    {
        dim3 grid(HID2 / 64, (N + 63) / 64);
        gemm_bias_kernel<HID, 2><<<grid, 256>>>(W2, b2, N, HID2);
    }
    // head
    head_kernel<<<(N + 127) / 128, 128>>>(W3, b3, out, N);
}

// round 9
// speedup vs baseline: 1.9506x; 1.9506x over previous
#include <cuda_runtime.h>
#include <cuda_bf16.h>
#include <stdint.h>

// Problem constants (fixed by the dataset)
#define N_NODES_MAX 50000
#define N_EDGES_MAX 800000
#define IN_F   128
#define HID    256
#define HID2   128
#define N_CLS  2

// ---------------- scratch (static device globals; no allocation) -------------
__device__ int   g_i64;                              // 1 if edge_index is int64
__device__ int   g_deg[N_NODES_MAX];
__device__ int   g_off[N_NODES_MAX + 1];
__device__ int   g_cursor[N_NODES_MAX];
__device__ int   g_part[256];                        // per-block degree sums
__device__ int   g_partoff[256];                     // exclusive prefix of block sums
__device__ __align__(16) float g_deginv[N_NODES_MAX];
__device__ __align__(16) int   g_src[N_EDGES_MAX];   // CSR: src node per in-edge (grouped by dst)
__device__ __align__(16) float g_agg[(size_t)N_NODES_MAX * HID];   // agg buffer (max width 256)
__device__ __align__(16) float g_h1 [(size_t)N_NODES_MAX * HID];   // layer-1 activations [N,256]
__device__ __align__(16) float g_h2 [(size_t)N_NODES_MAX * HID2];  // layer-2 activations [N,128]

__device__ __forceinline__ void f4_acc(float4& a, const float4& v) {
    a.x += v.x; a.y += v.y; a.z += v.z; a.w += v.w;
}

// Read edge value e from the row (idx=0) or col (idx=1) stream, honoring dtype.
__device__ __forceinline__ int edge_at(const void* edges, int E, int which, int e) {
    if (g_i64) {
        const long long* p = (const long long*)edges;
        return (int)p[(size_t)which * E + e];
    } else {
        const int* p = (const int*)edges;
        return p[(size_t)which * E + e];
    }
}

// ---------------- dtype detect -----------------------------------------------
__global__ void detect_dtype_kernel(const int* __restrict__ raw, int E) {
    __shared__ int nz;
    if (threadIdx.x == 0) nz = 0;
    __syncthreads();
    int samples = min(1024, E);
    for (int i = threadIdx.x; i < samples; i += blockDim.x) {
        if (raw[2 * i + 1] != 0) atomicOr(&nz, 1);
    }
    __syncthreads();
    if (threadIdx.x == 0) g_i64 = (nz == 0) ? 1 : 0;
}

// ---------------- CSR build --------------------------------------------------
__global__ void zero_deg_kernel(int n) {
    int i = blockIdx.x * blockDim.x + threadIdx.x;
    if (i < n) g_deg[i] = 0;
}

__global__ void hist_kernel(const void* __restrict__ edges, int E, int n) {
    int e = blockIdx.x * blockDim.x + threadIdx.x;
    if (e < E) {
        int d = edge_at(edges, E, 1, e);     // col
        d = max(0, min(d, n - 1));
        atomicAdd(&g_deg[d], 1);
    }
}

// --- parallel 3-pass scan: partials -> scan partials -> per-block rescan ------
__global__ void scan_partial_kernel(int n) {
    __shared__ int s[256];
    int b = blockIdx.x, t = threadIdx.x;
    int i = b * 256 + t;
    s[t] = (i < n) ? g_deg[i] : 0;
    __syncthreads();
    #pragma unroll
    for (int off = 128; off > 0; off >>= 1) {
        if (t < off) s[t] += s[t + off];
        __syncthreads();
    }
    if (t == 0) g_part[b] = s[0];
}

__global__ void scan_blocksums_kernel(int nb) {
    __shared__ int s[256];
    int t = threadIdx.x;
    int v = (t < nb) ? g_part[t] : 0;
    s[t] = v;
    __syncthreads();
    #pragma unroll
    for (int off = 1; off < 256; off <<= 1) {
        int u = (t >= off) ? s[t - off] : 0;
        __syncthreads();
        s[t] += u;
        __syncthreads();
    }
    if (t < nb) g_partoff[t] = s[t] - v;     // exclusive
}

__global__ void scan_final_kernel(int n) {
    __shared__ int s[256];
    int b = blockIdx.x, t = threadIdx.x;
    int i = b * 256 + t;
    int d = (i < n) ? g_deg[i] : 0;
    s[t] = d;
    __syncthreads();
    #pragma unroll
    for (int off = 1; off < 256; off <<= 1) {   // inclusive scan
        int u = (t >= off) ? s[t - off] : 0;
        __syncthreads();
        s[t] += u;
        __syncthreads();
    }
    int base = g_partoff[b];
    if (i < n) {
        int excl = base + s[t] - d;
        g_off[i]    = excl;
        g_cursor[i] = excl;
        g_deginv[i] = 1.0f / fmaxf((float)d, 1.0f);
        if (i == n - 1) g_off[n] = excl + d;
    }
}

__global__ void scatter_kernel(const void* __restrict__ edges, int E, int n) {
    int e = blockIdx.x * blockDim.x + threadIdx.x;
    if (e < E) {
        int d = edge_at(edges, E, 1, e);     // col (dst)
        d = max(0, min(d, n - 1));
        int s = edge_at(edges, E, 0, e);     // row (src)
        s = max(0, min(s, n - 1));
        int p = atomicAdd(&g_cursor[d], 1);
        if (p >= 0 && p < N_EDGES_MAX) g_src[p] = s;
    }
}

// ---------------- aggregation: warp per node, float4 gathers, 4-way unroll ----
template <int F, bool FROM_X>
__global__ void agg_kernel(const float* __restrict__ xin, int M) {
    const float* __restrict__ feat = FROM_X ? xin : (const float*)g_h1;
    int gw   = (blockIdx.x * blockDim.x + threadIdx.x) >> 5;
    int lane = threadIdx.x & 31;
    if (gw >= M) return;
    int beg = g_off[gw];
    int end = g_off[gw + 1];

    float4 acc0 = make_float4(0.f, 0.f, 0.f, 0.f);
    float4 acc1 = make_float4(0.f, 0.f, 0.f, 0.f);

    int i = beg;
    for (; i + 3 < end; i += 4) {
        int s0 = g_src[i], s1 = g_src[i + 1], s2 = g_src[i + 2], s3 = g_src[i + 3];
        const float4* r0 = (const float4*)(feat + (size_t)s0 * F);
        const float4* r1 = (const float4*)(feat + (size_t)s1 * F);
        const float4* r2 = (const float4*)(feat + (size_t)s2 * F);
        const float4* r3 = (const float4*)(feat + (size_t)s3 * F);
        float4 v0 = r0[lane], v1 = r1[lane], v2 = r2[lane], v3 = r3[lane];
        if (F == 256) {
            float4 w0 = r0[lane + 32], w1 = r1[lane + 32];
            float4 w2 = r2[lane + 32], w3 = r3[lane + 32];
            f4_acc(acc1, w0); f4_acc(acc1, w1); f4_acc(acc1, w2); f4_acc(acc1, w3);
        }
        f4_acc(acc0, v0); f4_acc(acc0, v1); f4_acc(acc0, v2); f4_acc(acc0, v3);
    }
    for (; i < end; ++i) {
        int s0 = g_src[i];
        const float4* r0 = (const float4*)(feat + (size_t)s0 * F);
        f4_acc(acc0, r0[lane]);
        if (F == 256) f4_acc(acc1, r0[lane + 32]);
    }

    float dinv = g_deginv[gw];
    float4* o = (float4*)((float*)g_agg + (size_t)gw * F);
    acc0.x *= dinv; acc0.y *= dinv; acc0.z *= dinv; acc0.w *= dinv;
    o[lane] = acc0;
    if (F == 256) {
        acc1.x *= dinv; acc1.y *= dinv; acc1.z *= dinv; acc1.w *= dinv;
        o[lane + 32] = acc1;
    }
}

// ---------------- tiled SGEMM: C[M,N] = g_agg[M,K] @ W[N,K]^T + bias, ReLU ----
// Tile 128x64 (MxN), BK=16, 256 threads, 8x4 micro-tile.
// Smem pitch padded +4 (132/68 floats): row pitch stays a multiple of 16 bytes
// so float4 LDS stay aligned (pitch 130 caused "misaligned address").
// OUT=1 -> writes g_h1 ; OUT=2 -> writes g_h2.
template <int K, int OUT>
__global__ void gemm_bias_kernel(const float* __restrict__ W,
                                 const float* __restrict__ bias,
                                 int M, int N) {
    const float* __restrict__ A = (const float*)g_agg;
    float* __restrict__ C = (OUT == 1) ? (float*)g_h1 : (float*)g_h2;

    __shared__ __align__(16) float As[16][132];
    __shared__ __align__(16) float Bs[16][68];

    int tid = threadIdx.x;            // 0..255
    int tx  = tid & 15;               // N micro: 4 cols each
    int ty  = tid >> 4;               // M micro: 8 rows each
    int m0  = blockIdx.y * 128;
    int n0  = blockIdx.x * 64;

    float acc[8][4];
    #pragma unroll
    for (int i = 0; i < 8; ++i)
        #pragma unroll
        for (int j = 0; j < 4; ++j) acc[i][j] = 0.f;

    int lr = tid >> 4;   // 0..15
    int lc = tid & 15;   // k within 16

    for (int k0 = 0; k0 < K; k0 += 16) {
        #pragma unroll
        for (int i = 0; i < 8; ++i) {
            int m = m0 + lr + i * 16;
            As[lc][lr + i * 16] = (m < M) ? A[(size_t)m * K + k0 + lc] : 0.f;
        }
        #pragma unroll
        for (int i = 0; i < 4; ++i) {
            int n = n0 + lr + i * 16;        // N is a multiple of 64
            Bs[lc][lr + i * 16] = W[(size_t)n * K + k0 + lc];
        }
        __syncthreads();

        #pragma unroll
        for (int kk = 0; kk < 16; ++kk) {
            float4 b4 = *(const float4*)&Bs[kk][tx * 4];
            float4 a0 = *(const float4*)&As[kk][ty * 8];
            float4 a1 = *(const float4*)&As[kk][ty * 8 + 4];
            float av[8] = {a0.x, a0.y, a0.z, a0.w, a1.x, a1.y, a1.z, a1.w};
            #pragma unroll
            for (int i = 0; i < 8; ++i) {
                acc[i][0] += av[i] * b4.x;
                acc[i][1] += av[i] * b4.y;
                acc[i][2] += av[i] * b4.z;
                acc[i][3] += av[i] * b4.w;
            }
        }
        __syncthreads();
    }

    float4 bv = *(const float4*)&bias[n0 + tx * 4];
    #pragma unroll
    for (int i = 0; i < 8; ++i) {
        int m = m0 + ty * 8 + i;
        if (m >= M) continue;
        float4 v;
        v.x = fmaxf(acc[i][0] + bv.x, 0.f);
        v.y = fmaxf(acc[i][1] + bv.y, 0.f);
        v.z = fmaxf(acc[i][2] + bv.z, 0.f);
        v.w = fmaxf(acc[i][3] + bv.w, 0.f);
        *(float4*)&C[(size_t)m * N + n0 + tx * 4] = v;
    }
}

// ---------------- final head: out[N,2] = g_h2 @ W3^T + b3 ---------------------
__global__ void head_kernel(const float* __restrict__ W3,
                            const float* __restrict__ b3,
                            float* __restrict__ out, int M) {
    __shared__ float w[2][HID2];
    __shared__ float b[2];
    for (int i = threadIdx.x; i < 2 * HID2; i += blockDim.x)
        w[i / HID2][i % HID2] = W3[i];
    if (threadIdx.x < 2) b[threadIdx.x] = b3[threadIdx.x];
    __syncthreads();

    int n = blockIdx.x * blockDim.x + threadIdx.x;
    if (n >= M) return;
    const float4* r = (const float4*)((const float*)g_h2 + (size_t)n * HID2);
    float s0 = b[0], s1 = b[1];
    #pragma unroll
    for (int i = 0; i < HID2 / 4; ++i) {
        float4 v = r[i];
        s0 += v.x * w[0][4 * i] + v.y * w[0][4 * i + 1] + v.z * w[0][4 * i + 2] + v.w * w[0][4 * i + 3];
        s1 += v.x * w[1][4 * i] + v.y * w[1][4 * i + 1] + v.z * w[1][4 * i + 2] + v.w * w[1][4 * i + 3];
    }
    out[(size_t)n * 2 + 0] = s0;
    out[(size_t)n * 2 + 1] = s1;
}

// ---------------- launch -----------------------------------------------------
extern "C" void kernel_launch(void* const* d_in, const int* in_sizes, int n_in,
                              void* d_out, int out_size) {
    const float* x     = (const float*)d_in[0];
    const void*  edges = d_in[1];            // [2, E], int32 OR int64 (detected on device)

    int wbase = 2;
    if (n_in >= 9 && in_sizes[2] <= 1) wbase = 3;
    const float* W1 = (const float*)d_in[wbase + 0];
    const float* b1 = (const float*)d_in[wbase + 1];
    const float* W2 = (const float*)d_in[wbase + 2];
    const float* b2 = (const float*)d_in[wbase + 3];
    const float* W3 = (const float*)d_in[wbase + 4];
    const float* b3 = (const float*)d_in[wbase + 5];
    float* out = (float*)d_out;

    int N = in_sizes[0] / IN_F;          // 50000
    int E = in_sizes[1] / 2;             // 800000
    if (N > N_NODES_MAX) N = N_NODES_MAX;
    if (E > N_EDGES_MAX) E = N_EDGES_MAX;

    int scanBlocks = (N + 255) / 256;    // 196 <= 256

    // dtype detect + CSR build
    detect_dtype_kernel<<<1, 256>>>((const int*)edges, E);
    zero_deg_kernel<<<(N + 255) / 256, 256>>>(N);
    hist_kernel<<<(E + 255) / 256, 256>>>(edges, E, N);
    scan_partial_kernel<<<scanBlocks, 256>>>(N);
    scan_blocksums_kernel<<<1, 256>>>(scanBlocks);
    scan_final_kernel<<<scanBlocks, 256>>>(N);
    scatter_kernel<<<(E + 255) / 256, 256>>>(edges, E, N);

    const int warpsPerBlock = 8;
    int aggBlocks = (N + warpsPerBlock - 1) / warpsPerBlock;

    // layer 1: agg(x) -> g_agg ; gemm(g_agg, W1) -> g_h1 (ReLU)
    agg_kernel<IN_F, true><<<aggBlocks, warpsPerBlock * 32>>>(x, N);
    {
        dim3 grid(HID / 64, (N + 127) / 128);
        gemm_bias_kernel<IN_F, 1><<<grid, 256>>>(W1, b1, N, HID);
    }
    // layer 2: agg(g_h1) -> g_agg ; gemm(g_agg, W2) -> g_h2 (ReLU)
    agg_kernel<HID, false><<<aggBlocks, warpsPerBlock * 32>>>(x, N);
    {
        dim3 grid(HID2 / 64, (N + 127) / 128);
        gemm_bias_kernel<HID, 2><<<grid, 256>>>(W2, b2, N, HID2);
    }
    // head
    head_kernel<<<(N + 127) / 128, 128>>>(W3, b3, out, N);
}